// round 15
// baseline (speedup 1.0000x reference)
#include <cuda_runtime.h>
#include <cuda_bf16.h>
#include <cstdint>
#include <cstddef>

#define BB 4
#define LL 4096
#define DD 1024
#define NK 256
#define KD 64
#define NH 4
#define CC 128
#define JJ 32
#define NCH 16
#define NTOT 512       // JJ*NCH
#define XT 192         // CC + KD

// ---------------- device scratch ----------------
__device__ float g_anorm[NK];
__device__ int   g_flag;
__device__ __align__(16) float g_X [NK][XT][KD];
__device__ __align__(16) float g_Nt[NK][CC][KD];
__device__ __align__(16) float g_P [NK][KD][KD];
__device__ __align__(16) float g_G [NK][KD][NTOT];
__device__ __align__(16) uint32_t g_LUT[NK][896];   // [0:256)TA [256:512)TAl [512:704)HA [704:896)HAl
__device__ __align__(256) __nv_bfloat16 g_Th[NK][KD][CC];
__device__ __align__(256) __nv_bfloat16 g_Tl[NK][KD][CC];
__device__ __align__(256) __nv_bfloat16 g_ubh[NK][NTOT][CC];
__device__ __align__(256) __nv_bfloat16 g_ubl[NK][NTOT][CC];
__device__ __align__(256) __nv_bfloat16 g_Hbh[NK][NTOT][KD];
__device__ __align__(256) __nv_bfloat16 g_Hbl[NK][NTOT][KD];

// ---------------- helpers ----------------
__device__ __forceinline__ uint32_t smem_u32(const void* p) {
    uint32_t a;
    asm("{ .reg .u64 t; cvta.to.shared.u64 t, %1; cvt.u32.u64 %0, t; }" : "=r"(a) : "l"(p));
    return a;
}
#define CP16(s, g) asm volatile("cp.async.cg.shared.global [%0], [%1], 16;" \
    :: "r"(s), "l"(__cvta_generic_to_global(g)))
#define CP_COMMIT() asm volatile("cp.async.commit_group;" ::: "memory")
#define CP_WAIT0()  asm volatile("cp.async.wait_group 0;" ::: "memory")
#define CP_WAIT1()  asm volatile("cp.async.wait_group 1;" ::: "memory")
#define CP_WAIT2()  asm volatile("cp.async.wait_group 2;" ::: "memory")

#define MMA16816(c0, c1, c2, c3, a0, a1, a2, a3, b0, b1) \
    asm volatile("mma.sync.aligned.m16n8k16.row.col.f32.bf16.bf16.f32 " \
        "{%0,%1,%2,%3}, {%4,%5,%6,%7}, {%8,%9}, {%0,%1,%2,%3};" \
        : "+f"(c0), "+f"(c1), "+f"(c2), "+f"(c3) \
        : "r"(a0), "r"(a1), "r"(a2), "r"(a3), "r"(b0), "r"(b1))

#define LDSM4(r, addr) \
    asm volatile("ldmatrix.sync.aligned.m8n8.x4.shared.b16 {%0,%1,%2,%3}, [%4];" \
        : "=r"((r)[0]), "=r"((r)[1]), "=r"((r)[2]), "=r"((r)[3]) : "r"(addr))

#define ASTRIDE 72   // smem row stride in bf16 (conflict-free LDSM phases)

__device__ __forceinline__ uint32_t pack_bf2(__nv_bfloat16 lo, __nv_bfloat16 hi) {
    return (uint32_t)__bfloat16_as_ushort(lo) | ((uint32_t)__bfloat16_as_ushort(hi) << 16);
}

// ---------------- 1) fused per-head L1 norm + flag ----------------
__global__ __launch_bounds__(256) void k_nf(const float* __restrict__ a) {
    int h = threadIdx.x;
    const float4* ap = (const float4*)(a + h * KD);
    float s = 0.f;
    #pragma unroll
    for (int i = 0; i < 16; i++) {
        float4 v = ap[i];
        s += fabsf(v.x) + fabsf(v.y) + fabsf(v.z) + fabsf(v.w);
    }
    g_anorm[h] = s;
    __shared__ float sm[8];
    float v = s;
    #pragma unroll
    for (int o = 16; o; o >>= 1) v += __shfl_down_sync(0xffffffffu, v, o);
    if ((h & 31) == 0) sm[h >> 5] = v;
    __syncthreads();
    if (h == 0) {
        float tot = 0.f;
        #pragma unroll
        for (int w = 0; w < 8; w++) tot += sm[w];
        g_flag = (tot / (float)NK > 1e-4f) ? 1 : 0;
    }
}

// ---------------- 2) precompute: trajectories -> LUTs, T(hi/lo), P ----
__global__ __launch_bounds__(256) void k_precomp(const float* __restrict__ a,
                                                 const float* __restrict__ b,
                                                 const float* __restrict__ c) {
    int h = blockIdx.x, tid = threadIdx.x;
    __shared__ float an[KD], cs[KD], bs[KD], ss[XT], kk[CC];
    if (tid < KD) {
        float av = a[h * KD + tid];
        an[tid] = g_flag ? (av / g_anorm[h]) : av;
        cs[tid] = c[h * KD + tid];
        bs[tid] = b[h * KD + tid];
    }
    __syncthreads();
    int wid = tid >> 5, lane = tid & 31;
    if (wid == 0) {
        float x0 = (lane == 0) ? 1.f : 0.f, x1 = 0.f;
        float alo = an[lane], ahi = an[lane + 32];
        g_X[h][0][lane] = x0; g_X[h][0][lane + 32] = x1;
        for (int t = 1; t < XT; t++) {
            float last = __shfl_sync(0xffffffffu, x1, 31);
            float top  = __shfl_sync(0xffffffffu, x0, 31);
            float sx0  = __shfl_up_sync(0xffffffffu, x0, 1);
            float sx1  = __shfl_up_sync(0xffffffffu, x1, 1);
            if (lane == 0) { sx0 = 0.f; sx1 = top; }
            x0 = fmaf(alo, last, sx0);
            x1 = fmaf(ahi, last, sx1);
            g_X[h][t][lane] = x0; g_X[h][t][lane + 32] = x1;
        }
    } else if (wid == 1) {
        float x0 = bs[lane], x1 = bs[lane + 32];
        float alo = an[lane], ahi = an[lane + 32];
        g_Nt[h][CC - 1][lane] = x0; g_Nt[h][CC - 1][lane + 32] = x1;
        for (int t = 1; t < CC; t++) {
            float last = __shfl_sync(0xffffffffu, x1, 31);
            float top  = __shfl_sync(0xffffffffu, x0, 31);
            float sx0  = __shfl_up_sync(0xffffffffu, x0, 1);
            float sx1  = __shfl_up_sync(0xffffffffu, x1, 1);
            if (lane == 0) { sx0 = 0.f; sx1 = top; }
            x0 = fmaf(alo, last, sx0);
            x1 = fmaf(ahi, last, sx1);
            g_Nt[h][CC - 1 - t][lane] = x0; g_Nt[h][CC - 1 - t][lane + 32] = x1;
        }
    }
    __syncthreads();
    if (tid >= 1 && tid < XT) {
        float acc = 0.f;
        #pragma unroll 16
        for (int i = 0; i < KD; i++) acc = fmaf(cs[i], g_X[h][tid][i], acc);
        ss[tid] = acc;
    }
    if (tid == 0) ss[0] = 0.f;
    if (tid < CC) {
        float acc = 0.f;
        #pragma unroll 16
        for (int i = 0; i < KD; i++) acc = fmaf(cs[i], g_Nt[h][CC - 1 - tid][i], acc);
        kk[tid] = acc;
    }
    for (int idx = tid; idx < KD * KD; idx += 256) {
        int i2 = idx >> 6, j2 = idx & 63;
        g_P[h][i2][j2] = g_X[h][CC + j2][i2];
    }
    __syncthreads();
    // packed A-fragment LUTs for GEMM-B
    {
        int x = tid;                                  // 0..255
        float kc_ = (x >= 128) ? kk[x - 128] : 0.f;   // kp[x]
        float kp_ = (x >= 129) ? kk[x - 129] : 0.f;   // kp[x-1]
        __nv_bfloat16 ch = __float2bfloat16(kc_), ph = __float2bfloat16(kp_);
        g_LUT[h][x] = pack_bf2(ch, ph);
        __nv_bfloat16 cl = __float2bfloat16(kc_ - __bfloat162float(ch));
        __nv_bfloat16 pl = __float2bfloat16(kp_ - __bfloat162float(ph));
        g_LUT[h][256 + x] = pack_bf2(cl, pl);
        if (x < 192) {
            float s0 = ss[x];
            float s1 = (x + 1 < XT) ? ss[x + 1] : 0.f;
            __nv_bfloat16 s0h = __float2bfloat16(s0), s1h = __float2bfloat16(s1);
            g_LUT[h][512 + x] = pack_bf2(s0h, s1h);
            __nv_bfloat16 s0l = __float2bfloat16(s0 - __bfloat162float(s0h));
            __nv_bfloat16 s1l = __float2bfloat16(s1 - __bfloat162float(s1h));
            g_LUT[h][704 + x] = pack_bf2(s0l, s1l);
        }
    }
    // T[i][sigma] = Nt[sigma][i]
    for (int idx = tid; idx < KD * CC; idx += 256) {
        int i2 = idx >> 7, sg = idx & 127;
        float v = g_Nt[h][sg][i2];
        __nv_bfloat16 hi = __float2bfloat16(v);
        __nv_bfloat16 lo = __float2bfloat16(v - __bfloat162float(hi));
        g_Th[h][i2][sg] = hi;
        g_Tl[h][i2][sg] = lo;
    }
}

// ---------------- 3) transpose u -> ub hi/lo (coalesced 256B writes) ----
__global__ __launch_bounds__(256) void k_tr(const float* __restrict__ u) {
    __shared__ float ts[CC][65];
    int bid = blockIdx.x;
    int dblk = bid & 15, b = (bid >> 4) & 3, j = bid >> 6;
    int tid = threadIdx.x;
    #pragma unroll
    for (int it = 0; it < 8; it++) {
        int idx = tid + 256 * it;            // 2048 float4
        int sg = idx >> 4, dq = idx & 15;
        float4 v = *(const float4*)&u[((size_t)(b * LL + j * CC + sg)) * DD + dblk * 64 + dq * 4];
        ts[sg][dq * 4 + 0] = v.x; ts[sg][dq * 4 + 1] = v.y;
        ts[sg][dq * 4 + 2] = v.z; ts[sg][dq * 4 + 3] = v.w;
    }
    __syncthreads();
    #pragma unroll
    for (int it = 0; it < 4; it++) {
        int item = tid + 256 * it;           // 1024 items = 64 dl x 16 seg
        int seg = item & 15, dl = item >> 4;
        int dg = dblk * 64 + dl;
        int h = dg >> 2, r = dg & 3;
        int n = j * NCH + b * 4 + r;
        uint32_t hv[4], lv[4];
        #pragma unroll
        for (int t = 0; t < 8; t += 2) {
            float f0 = ts[seg * 8 + t][dl];
            float f1 = ts[seg * 8 + t + 1][dl];
            __nv_bfloat16 h0 = __float2bfloat16(f0);
            __nv_bfloat16 h1 = __float2bfloat16(f1);
            __nv_bfloat16 l0 = __float2bfloat16(f0 - __bfloat162float(h0));
            __nv_bfloat16 l1 = __float2bfloat16(f1 - __bfloat162float(h1));
            hv[t >> 1] = pack_bf2(h0, h1);
            lv[t >> 1] = pack_bf2(l0, l1);
        }
        *(uint4*)&g_ubh[h][n][seg * 8] = make_uint4(hv[0], hv[1], hv[2], hv[3]);
        *(uint4*)&g_ubl[h][n][seg * 8] = make_uint4(lv[0], lv[1], lv[2], lv[3]);
    }
}

// ================ GEMM-A: G[64,512] = T @ ub^T (3 hi/lo terms) ==========
#define GA_AROWS 64
#define GA_AELE  (GA_AROWS * ASTRIDE)
#define GA_ABYTES (GA_AELE * 2)
#define GA_BELE  (128 * ASTRIDE)
#define GA_STG   (GA_ABYTES + GA_BELE * 2)
#define GA_SMEM  (2 * GA_STG)

__global__ __launch_bounds__(128) void k_gemm_g() {
    extern __shared__ char dsm[];
    int q = blockIdx.x, h = blockIdx.y, tid = threadIdx.x;
    int wid = tid >> 5, lane = tid & 31;
    int n0 = q * 128;
    int warpM = wid & 1, warpN = wid >> 1;
    int m0 = warpM * 32, nw0 = warpN * 64;
    int tg = lane >> 2, tq = lane & 3;
    uint32_t sbase = smem_u32(dsm);
    uint32_t aOff = (uint32_t)(((m0 + (lane & 15)) * ASTRIDE + (lane >> 4) * 8) * 2);
    uint32_t bOff = (uint32_t)(((nw0 + (lane & 7) + ((lane >> 4) & 1) * 8) * ASTRIDE
                                + ((lane >> 3) & 1) * 8) * 2);

    float acc[2][8][4];
    #pragma unroll
    for (int mf = 0; mf < 2; mf++)
        #pragma unroll
        for (int nf = 0; nf < 8; nf++)
            #pragma unroll
            for (int v = 0; v < 4; v++) acc[mf][nf][v] = 0.f;

    const int NC = 6;
    #define GA_LOAD(c) do { \
        int st_ = (c) & 1; \
        uint32_t sA = sbase + st_ * GA_STG; \
        uint32_t sB = sA + GA_ABYTES; \
        int kc = ((c) & 1) * 64; \
        const __nv_bfloat16* asrc = ((c) >= 4) ? &g_Tl[h][0][kc] : &g_Th[h][0][kc]; \
        const __nv_bfloat16* bsrc = ((c) == 2 || (c) == 3) ? &g_ubl[h][n0][kc] : &g_ubh[h][n0][kc]; \
        _Pragma("unroll") \
        for (int it = 0; it < 4; it++) { \
            int idx = tid + 128 * it; \
            int row = idx >> 3, cu = idx & 7; \
            CP16(sA + row * (ASTRIDE * 2) + cu * 16, (const char*)asrc + row * 256 + cu * 16); \
        } \
        _Pragma("unroll") \
        for (int it = 0; it < 8; it++) { \
            int idx = tid + 128 * it; \
            int row = idx >> 3, cu = idx & 7; \
            CP16(sB + row * (ASTRIDE * 2) + cu * 16, (const char*)bsrc + row * 256 + cu * 16); \
        } \
        CP_COMMIT(); \
    } while (0)

    GA_LOAD(0);
    #pragma unroll 1
    for (int c = 0; c < NC; c++) {
        if (c + 1 < NC) { GA_LOAD(c + 1); CP_WAIT1(); }
        else            { CP_WAIT0(); }
        __syncthreads();
        uint32_t sA = sbase + (c & 1) * GA_STG;
        uint32_t sB = sA + GA_ABYTES;
        uint32_t aAddr = sA + aOff;
        uint32_t bAddr = sB + bOff;
        #pragma unroll
        for (int ks = 0; ks < 4; ks++) {
            uint32_t afr[2][4];
            LDSM4(afr[0], aAddr + ks * 32);
            LDSM4(afr[1], aAddr + 16 * ASTRIDE * 2 + ks * 32);
            #pragma unroll
            for (int p = 0; p < 4; p++) {
                uint32_t bfr[4];
                LDSM4(bfr, bAddr + p * 16 * ASTRIDE * 2 + ks * 32);
                #pragma unroll
                for (int sub = 0; sub < 2; sub++) {
                    int nf = p * 2 + sub;
                    uint32_t b0 = bfr[sub * 2], b1 = bfr[sub * 2 + 1];
                    #pragma unroll
                    for (int mf = 0; mf < 2; mf++)
                        MMA16816(acc[mf][nf][0], acc[mf][nf][1], acc[mf][nf][2], acc[mf][nf][3],
                                 afr[mf][0], afr[mf][1], afr[mf][2], afr[mf][3], b0, b1);
                }
            }
        }
        __syncthreads();
    }
    #undef GA_LOAD
    #pragma unroll
    for (int mf = 0; mf < 2; mf++) {
        int i = m0 + mf * 16 + tg;
        #pragma unroll
        for (int nf = 0; nf < 8; nf++) {
            int n = n0 + nw0 + nf * 8 + tq * 2;
            *(float2*)&g_G[h][i][n]     = make_float2(acc[mf][nf][0], acc[mf][nf][1]);
            *(float2*)&g_G[h][i + 8][n] = make_float2(acc[mf][nf][2], acc[mf][nf][3]);
        }
    }
}

// ---- scan: H_j = P H_{j-1} + G_j ; G prefetch, 1 barrier/iter ----------
__global__ __launch_bounds__(64) void k_scan() {
    int h = blockIdx.x >> 2, cq = blockIdx.x & 3, i = threadIdx.x;
    float P[KD];
    #pragma unroll
    for (int kq = 0; kq < KD; kq += 4) {
        float4 p = *(const float4*)&g_P[h][i][kq];
        P[kq] = p.x; P[kq + 1] = p.y; P[kq + 2] = p.z; P[kq + 3] = p.w;
    }
    __shared__ float hs[2][KD][4];
    float hv[4] = {0.f, 0.f, 0.f, 0.f};
    float4 gnext = *(const float4*)&g_G[h][i][cq * 4];
    #pragma unroll 1
    for (int j = 0; j < JJ; j++) {
        int buf = j & 1;
        #pragma unroll
        for (int cch = 0; cch < 4; cch++) {
            int n = j * NCH + cq * 4 + cch;
            __nv_bfloat16 hi = __float2bfloat16(hv[cch]);
            g_Hbh[h][n][i] = hi;
            g_Hbl[h][n][i] = __float2bfloat16(hv[cch] - __bfloat162float(hi));
        }
        *(float4*)&hs[buf][i][0] = make_float4(hv[0], hv[1], hv[2], hv[3]);
        float4 gcur = gnext;
        __syncthreads();
        if (j + 1 < JJ)
            gnext = *(const float4*)&g_G[h][i][(j + 1) * NCH + cq * 4];
        float acc[4] = {gcur.x, gcur.y, gcur.z, gcur.w};
        #pragma unroll
        for (int kq = 0; kq < KD; kq++) {
            float4 hk = *(const float4*)&hs[buf][kq][0];
            acc[0] = fmaf(P[kq], hk.x, acc[0]);
            acc[1] = fmaf(P[kq], hk.y, acc[1]);
            acc[2] = fmaf(P[kq], hk.z, acc[2]);
            acc[3] = fmaf(P[kq], hk.w, acc[3]);
        }
        hv[0] = acc[0]; hv[1] = acc[1]; hv[2] = acc[2]; hv[3] = acc[3];
    }
}

// ==== GEMM-B: y = [Toep(k)|Hank(s)] @ [u|H]^T — A from LUT, B streamed ===
// 256 threads: 8 warps = 4 balanced row-pairs x 2 column halves.
// Each thread: acc[2][4][4] = 32 regs (halved vs 128-thread version).
#define YSTG  (64 * ASTRIDE * 2)     // 9216 B : one 64-row B tile
#define YSMEM (4 * YSTG)             // 4-stage ring

__global__ __launch_bounds__(256) void k_gemm_y(float* __restrict__ y) {
    extern __shared__ char dsm[];
    __shared__ uint32_t sLUT[896];
    int qb = blockIdx.x, h = blockIdx.y, tid = threadIdx.x;
    int wid = tid >> 5, lane = tid & 31;
    int wm = wid & 3, ph2 = wid >> 2;   // row-pair id, column half
    int n0 = qb * 64;
    int rb0 = wm * 16;                  // mf0 row block
    int rb1 = 112 - wm * 16;            // mf1 row block (balanced pairing)
    int tg = lane >> 2, tq = lane & 3;
    uint32_t smStg = smem_u32(dsm);
    // B fragment offset: this warp's column half starts at B-row ph2*32
    uint32_t bOff = (uint32_t)(((ph2 * 32 + (lane & 7) + ((lane >> 4) & 1) * 8) * ASTRIDE
                                + ((lane >> 3) & 1) * 8) * 2);
    #pragma unroll
    for (int it = 0; it < 4; it++) {
        int idx = tid + 256 * it;
        if (idx < 896) sLUT[idx] = g_LUT[h][idx];
    }

    float acc[2][4][4];
    #pragma unroll
    for (int mf = 0; mf < 2; mf++)
        #pragma unroll
        for (int nf = 0; nf < 4; nf++)
            #pragma unroll
            for (int v = 0; v < 4; v++) acc[mf][nf][v] = 0.f;

    #define YB_LOAD(t) do { \
        const __nv_bfloat16* bsrc; int brs; \
        switch (t) { \
            case 0: bsrc = &g_ubh[h][n0][0];  brs = 256; break; \
            case 1: bsrc = &g_ubh[h][n0][64]; brs = 256; break; \
            case 2: bsrc = &g_Hbh[h][n0][0];  brs = 128; break; \
            case 3: bsrc = &g_ubl[h][n0][0];  brs = 256; break; \
            case 4: bsrc = &g_ubl[h][n0][64]; brs = 256; break; \
            default: bsrc = &g_Hbl[h][n0][0]; brs = 128; break; } \
        uint32_t sB = smStg + ((t) & 3) * YSTG; \
        _Pragma("unroll") \
        for (int it = 0; it < 2; it++) { \
            int idx = tid + 256 * it;        /* 512 = 64 rows x 8 cu */ \
            int row = idx >> 3, cu = idx & 7; \
            CP16(sB + row * (ASTRIDE * 2) + cu * 16, (const char*)bsrc + row * brs + cu * 16); \
        } \
        CP_COMMIT(); \
    } while (0)

    // One B tile, npass W-terms; B fragments loaded once per ks.
    #define Y_TILE(hank, kc, npass) do { \
        _Pragma("unroll") \
        for (int ks = 0; ks < 4; ks++) { \
            int sig0 = (kc) * 64 + ks * 16; \
            bool live0 = true, live1 = true; \
            if (!(hank)) { \
                live1 = (sig0 <= rb1 + 15); \
                if (!live1) continue;           /* rb1 > rb0: both dead */ \
                live0 = (sig0 <= rb0 + 15); \
            } \
            uint32_t bfr[2][4]; \
            _Pragma("unroll") \
            for (int p = 0; p < 2; p++) \
                LDSM4(bfr[p], bAddr + p * 16 * ASTRIDE * 2 + ks * 32); \
            _Pragma("unroll") \
            for (int term = 0; term < (npass); term++) { \
                const uint32_t* lutp = (hank) ? (term ? sLUT + 704 : sLUT + 512) \
                                              : (term ? sLUT + 256 : sLUT); \
                uint32_t A0[4], A1[4]; \
                if (hank) { \
                    int x0 = rb0 + 1 + ks * 16 + tq * 2 + tg; \
                    int x1 = rb1 + 1 + ks * 16 + tq * 2 + tg; \
                    uint32_t h0 = lutp[x0], h1 = lutp[x0 + 8], h2 = lutp[x0 + 16]; \
                    uint32_t h3 = lutp[x1], h4 = lutp[x1 + 8], h5 = lutp[x1 + 16]; \
                    A0[0] = h0; A0[1] = h1; A0[2] = h1; A0[3] = h2; \
                    A1[0] = h3; A1[1] = h4; A1[2] = h4; A1[3] = h5; \
                } else { \
                    int x0 = 128 + rb0 + tg - sig0 - tq * 2; \
                    int x1 = 128 + rb1 + tg - sig0 - tq * 2; \
                    uint32_t w0 = lutp[x0], w1 = lutp[x0 + 8], w2 = lutp[x0 - 8]; \
                    uint32_t w3 = lutp[x1], w4 = lutp[x1 + 8], w5 = lutp[x1 - 8]; \
                    A0[0] = w0; A0[1] = w1; A0[2] = w2; A0[3] = w0; \
                    A1[0] = w3; A1[1] = w4; A1[2] = w5; A1[3] = w3; \
                } \
                _Pragma("unroll") \
                for (int p = 0; p < 2; p++) { \
                    _Pragma("unroll") \
                    for (int sub = 0; sub < 2; sub++) { \
                        int nf = p * 2 + sub; \
                        uint32_t b0 = bfr[p][sub * 2], b1 = bfr[p][sub * 2 + 1]; \
                        if (live0) \
                            MMA16816(acc[0][nf][0], acc[0][nf][1], acc[0][nf][2], acc[0][nf][3], \
                                     A0[0], A0[1], A0[2], A0[3], b0, b1); \
                        if (live1) \
                            MMA16816(acc[1][nf][0], acc[1][nf][1], acc[1][nf][2], acc[1][nf][3], \
                                     A1[0], A1[1], A1[2], A1[3], b0, b1); \
                    } \
                } \
            } \
        } \
    } while (0)

    YB_LOAD(0); YB_LOAD(1); YB_LOAD(2);
    #pragma unroll 1
    for (int t = 0; t < 6; t++) {
        if (t <= 3)      CP_WAIT2();
        else if (t == 4) CP_WAIT1();
        else             CP_WAIT0();
        __syncthreads();
        if (t + 3 < 6) YB_LOAD(t + 3);
        uint32_t bAddr = smStg + (t & 3) * YSTG + bOff;
        switch (t) {
            case 0: Y_TILE(0, 0, 2); break;
            case 1: Y_TILE(0, 1, 2); break;
            case 2: Y_TILE(1, 0, 2); break;
            case 3: Y_TILE(0, 0, 1); break;
            case 4: Y_TILE(0, 1, 1); break;
            default: Y_TILE(1, 0, 1); break;
        }
    }
    #undef Y_TILE
    #undef YB_LOAD

    // epilogue -> y (this warp's 32-column slice)
    #pragma unroll
    for (int mf = 0; mf < 2; mf++) {
        int tau = (mf == 0 ? rb0 : rb1) + tg;
        #pragma unroll
        for (int nf = 0; nf < 4; nf++) {
            int n = n0 + ph2 * 32 + nf * 8 + tq * 2;
            int j = n >> 4, b = (n >> 2) & 3, r = n & 3;
            size_t base = ((size_t)(b * LL + j * CC + tau)) * DD + h * NH + r;
            *(float2*)&y[base]          = make_float2(acc[mf][nf][0], acc[mf][nf][1]);
            *(float2*)&y[base + 8 * DD] = make_float2(acc[mf][nf][2], acc[mf][nf][3]);
        }
    }
}

// ---------------- launch ----------------
extern "C" void kernel_launch(void* const* d_in, const int* in_sizes, int n_in,
                              void* d_out, int out_size) {
    const float* u = (const float*)d_in[0];
    const float* a = (const float*)d_in[1];
    const float* b = (const float*)d_in[2];
    const float* c = (const float*)d_in[3];
    float* y = (float*)d_out;

    cudaFuncSetAttribute(k_gemm_g, cudaFuncAttributeMaxDynamicSharedMemorySize, GA_SMEM);
    cudaFuncSetAttribute(k_gemm_y, cudaFuncAttributeMaxDynamicSharedMemorySize, YSMEM);

    // fork: k_tr (memory) runs concurrently with k_nf+k_precomp (compute)
    cudaStream_t s1;
    cudaEvent_t e0, e1;
    bool forked = (cudaStreamCreateWithFlags(&s1, cudaStreamNonBlocking) == cudaSuccess) &&
                  (cudaEventCreateWithFlags(&e0, cudaEventDisableTiming) == cudaSuccess) &&
                  (cudaEventCreateWithFlags(&e1, cudaEventDisableTiming) == cudaSuccess);

    if (forked) {
        cudaEventRecord(e0, 0);
        cudaStreamWaitEvent(s1, e0, 0);
        k_tr<<<2048, 256, 0, s1>>>(u);
        cudaEventRecord(e1, s1);
    } else {
        k_tr<<<2048, 256>>>(u);
    }
    k_nf<<<1, 256>>>(a);
    k_precomp<<<NK, 256>>>(a, b, c);
    if (forked) cudaStreamWaitEvent(0, e1, 0);
    k_gemm_g<<<dim3(4, NK), 128, GA_SMEM>>>();
    k_scan<<<NK * 4, 64>>>();
    k_gemm_y<<<dim3(8, NK), 256, YSMEM>>>(y);
    // s1/e0/e1 intentionally not destroyed (graph-capture safety).
}

// round 16
// speedup vs baseline: 1.0852x; 1.0852x over previous
#include <cuda_runtime.h>
#include <cuda_bf16.h>
#include <cstdint>
#include <cstddef>

#define BB 4
#define LL 4096
#define DD 1024
#define NK 256
#define KD 64
#define NH 4
#define CC 128
#define JJ 32
#define NCH 16
#define NTOT 512       // JJ*NCH
#define XT 192         // CC + KD

// ---------------- device scratch ----------------
__device__ float g_anorm[NK];
__device__ int   g_flag;
__device__ __align__(16) float g_X [NK][XT][KD];
__device__ __align__(16) float g_Nt[NK][CC][KD];
__device__ __align__(16) float g_P [NK][KD][KD];
__device__ __align__(16) float g_G [NK][KD][NTOT];
__device__ __align__(16) uint32_t g_LUT[NK][896];   // [0:256)TA [256:512)TAl [512:704)HA [704:896)HAl
__device__ __align__(256) __nv_bfloat16 g_Th[NK][KD][CC];
__device__ __align__(256) __nv_bfloat16 g_Tl[NK][KD][CC];
__device__ __align__(256) __nv_bfloat16 g_ubh[NK][NTOT][CC];
__device__ __align__(256) __nv_bfloat16 g_ubl[NK][NTOT][CC];
__device__ __align__(256) __nv_bfloat16 g_Hbh[NK][NTOT][KD];
__device__ __align__(256) __nv_bfloat16 g_Hbl[NK][NTOT][KD];

// ---------------- helpers ----------------
__device__ __forceinline__ uint32_t smem_u32(const void* p) {
    uint32_t a;
    asm("{ .reg .u64 t; cvta.to.shared.u64 t, %1; cvt.u32.u64 %0, t; }" : "=r"(a) : "l"(p));
    return a;
}
#define CP16(s, g) asm volatile("cp.async.cg.shared.global [%0], [%1], 16;" \
    :: "r"(s), "l"(__cvta_generic_to_global(g)))
#define CP_COMMIT() asm volatile("cp.async.commit_group;" ::: "memory")
#define CP_WAIT0()  asm volatile("cp.async.wait_group 0;" ::: "memory")
#define CP_WAIT1()  asm volatile("cp.async.wait_group 1;" ::: "memory")
#define CP_WAIT2()  asm volatile("cp.async.wait_group 2;" ::: "memory")

#define MMA16816(c0, c1, c2, c3, a0, a1, a2, a3, b0, b1) \
    asm volatile("mma.sync.aligned.m16n8k16.row.col.f32.bf16.bf16.f32 " \
        "{%0,%1,%2,%3}, {%4,%5,%6,%7}, {%8,%9}, {%0,%1,%2,%3};" \
        : "+f"(c0), "+f"(c1), "+f"(c2), "+f"(c3) \
        : "r"(a0), "r"(a1), "r"(a2), "r"(a3), "r"(b0), "r"(b1))

#define LDSM4(r, addr) \
    asm volatile("ldmatrix.sync.aligned.m8n8.x4.shared.b16 {%0,%1,%2,%3}, [%4];" \
        : "=r"((r)[0]), "=r"((r)[1]), "=r"((r)[2]), "=r"((r)[3]) : "r"(addr))

#define ASTRIDE 72   // smem row stride in bf16 (conflict-free LDSM phases)

__device__ __forceinline__ uint32_t pack_bf2(__nv_bfloat16 lo, __nv_bfloat16 hi) {
    return (uint32_t)__bfloat16_as_ushort(lo) | ((uint32_t)__bfloat16_as_ushort(hi) << 16);
}

// ---------------- 1) fused per-head L1 norm + flag ----------------
__global__ __launch_bounds__(256) void k_nf(const float* __restrict__ a) {
    int h = threadIdx.x;
    const float4* ap = (const float4*)(a + h * KD);
    float s = 0.f;
    #pragma unroll
    for (int i = 0; i < 16; i++) {
        float4 v = ap[i];
        s += fabsf(v.x) + fabsf(v.y) + fabsf(v.z) + fabsf(v.w);
    }
    g_anorm[h] = s;
    __shared__ float sm[8];
    float v = s;
    #pragma unroll
    for (int o = 16; o; o >>= 1) v += __shfl_down_sync(0xffffffffu, v, o);
    if ((h & 31) == 0) sm[h >> 5] = v;
    __syncthreads();
    if (h == 0) {
        float tot = 0.f;
        #pragma unroll
        for (int w = 0; w < 8; w++) tot += sm[w];
        g_flag = (tot / (float)NK > 1e-4f) ? 1 : 0;
    }
}

// ---------------- 2) precompute: trajectories -> LUTs, T(hi/lo), P ----
__global__ __launch_bounds__(256) void k_precomp(const float* __restrict__ a,
                                                 const float* __restrict__ b,
                                                 const float* __restrict__ c) {
    int h = blockIdx.x, tid = threadIdx.x;
    __shared__ float an[KD], cs[KD], bs[KD], ss[XT], kk[CC];
    if (tid < KD) {
        float av = a[h * KD + tid];
        an[tid] = g_flag ? (av / g_anorm[h]) : av;
        cs[tid] = c[h * KD + tid];
        bs[tid] = b[h * KD + tid];
    }
    __syncthreads();
    int wid = tid >> 5, lane = tid & 31;
    if (wid == 0) {
        float x0 = (lane == 0) ? 1.f : 0.f, x1 = 0.f;
        float alo = an[lane], ahi = an[lane + 32];
        g_X[h][0][lane] = x0; g_X[h][0][lane + 32] = x1;
        for (int t = 1; t < XT; t++) {
            float last = __shfl_sync(0xffffffffu, x1, 31);
            float top  = __shfl_sync(0xffffffffu, x0, 31);
            float sx0  = __shfl_up_sync(0xffffffffu, x0, 1);
            float sx1  = __shfl_up_sync(0xffffffffu, x1, 1);
            if (lane == 0) { sx0 = 0.f; sx1 = top; }
            x0 = fmaf(alo, last, sx0);
            x1 = fmaf(ahi, last, sx1);
            g_X[h][t][lane] = x0; g_X[h][t][lane + 32] = x1;
        }
    } else if (wid == 1) {
        float x0 = bs[lane], x1 = bs[lane + 32];
        float alo = an[lane], ahi = an[lane + 32];
        g_Nt[h][CC - 1][lane] = x0; g_Nt[h][CC - 1][lane + 32] = x1;
        for (int t = 1; t < CC; t++) {
            float last = __shfl_sync(0xffffffffu, x1, 31);
            float top  = __shfl_sync(0xffffffffu, x0, 31);
            float sx0  = __shfl_up_sync(0xffffffffu, x0, 1);
            float sx1  = __shfl_up_sync(0xffffffffu, x1, 1);
            if (lane == 0) { sx0 = 0.f; sx1 = top; }
            x0 = fmaf(alo, last, sx0);
            x1 = fmaf(ahi, last, sx1);
            g_Nt[h][CC - 1 - t][lane] = x0; g_Nt[h][CC - 1 - t][lane + 32] = x1;
        }
    }
    __syncthreads();
    if (tid >= 1 && tid < XT) {
        float acc = 0.f;
        #pragma unroll 16
        for (int i = 0; i < KD; i++) acc = fmaf(cs[i], g_X[h][tid][i], acc);
        ss[tid] = acc;
    }
    if (tid == 0) ss[0] = 0.f;
    if (tid < CC) {
        float acc = 0.f;
        #pragma unroll 16
        for (int i = 0; i < KD; i++) acc = fmaf(cs[i], g_Nt[h][CC - 1 - tid][i], acc);
        kk[tid] = acc;
    }
    for (int idx = tid; idx < KD * KD; idx += 256) {
        int i2 = idx >> 6, j2 = idx & 63;
        g_P[h][i2][j2] = g_X[h][CC + j2][i2];
    }
    __syncthreads();
    // packed A-fragment LUTs for GEMM-B
    {
        int x = tid;                                  // 0..255
        float kc_ = (x >= 128) ? kk[x - 128] : 0.f;   // kp[x]
        float kp_ = (x >= 129) ? kk[x - 129] : 0.f;   // kp[x-1]
        __nv_bfloat16 ch = __float2bfloat16(kc_), ph = __float2bfloat16(kp_);
        g_LUT[h][x] = pack_bf2(ch, ph);
        __nv_bfloat16 cl = __float2bfloat16(kc_ - __bfloat162float(ch));
        __nv_bfloat16 pl = __float2bfloat16(kp_ - __bfloat162float(ph));
        g_LUT[h][256 + x] = pack_bf2(cl, pl);
        if (x < 192) {
            float s0 = ss[x];
            float s1 = (x + 1 < XT) ? ss[x + 1] : 0.f;
            __nv_bfloat16 s0h = __float2bfloat16(s0), s1h = __float2bfloat16(s1);
            g_LUT[h][512 + x] = pack_bf2(s0h, s1h);
            __nv_bfloat16 s0l = __float2bfloat16(s0 - __bfloat162float(s0h));
            __nv_bfloat16 s1l = __float2bfloat16(s1 - __bfloat162float(s1h));
            g_LUT[h][704 + x] = pack_bf2(s0l, s1l);
        }
    }
    // T[i][sigma] = Nt[sigma][i]
    for (int idx = tid; idx < KD * CC; idx += 256) {
        int i2 = idx >> 7, sg = idx & 127;
        float v = g_Nt[h][sg][i2];
        __nv_bfloat16 hi = __float2bfloat16(v);
        __nv_bfloat16 lo = __float2bfloat16(v - __bfloat162float(hi));
        g_Th[h][i2][sg] = hi;
        g_Tl[h][i2][sg] = lo;
    }
}

// ---- 3) transpose u -> ub hi/lo (half-chunk blocks for occupancy) ------
__global__ __launch_bounds__(256) void k_tr(const float* __restrict__ u) {
    __shared__ float ts[64][65];
    int bid = blockIdx.x;
    int half = bid & 1, bid2 = bid >> 1;
    int dblk = bid2 & 15, b = (bid2 >> 4) & 3, j = bid2 >> 6;
    int sbase = half * 64;
    int tid = threadIdx.x;
    #pragma unroll
    for (int it = 0; it < 4; it++) {
        int idx = tid + 256 * it;            // 1024 float4 = 64 sg x 16 dq
        int sg = idx >> 4, dq = idx & 15;
        float4 v = *(const float4*)&u[((size_t)(b * LL + j * CC + sbase + sg)) * DD
                                      + dblk * 64 + dq * 4];
        ts[sg][dq * 4 + 0] = v.x; ts[sg][dq * 4 + 1] = v.y;
        ts[sg][dq * 4 + 2] = v.z; ts[sg][dq * 4 + 3] = v.w;
    }
    __syncthreads();
    #pragma unroll
    for (int it = 0; it < 2; it++) {
        int item = tid + 256 * it;           // 512 items = 64 dl x 8 segl
        int segl = item & 7, dl = item >> 3;
        int dg = dblk * 64 + dl;
        int h = dg >> 2, r = dg & 3;
        int n = j * NCH + b * 4 + r;
        uint32_t hv[4], lv[4];
        #pragma unroll
        for (int t = 0; t < 8; t += 2) {
            float f0 = ts[segl * 8 + t][dl];
            float f1 = ts[segl * 8 + t + 1][dl];
            __nv_bfloat16 h0 = __float2bfloat16(f0);
            __nv_bfloat16 h1 = __float2bfloat16(f1);
            __nv_bfloat16 l0 = __float2bfloat16(f0 - __bfloat162float(h0));
            __nv_bfloat16 l1 = __float2bfloat16(f1 - __bfloat162float(h1));
            hv[t >> 1] = pack_bf2(h0, h1);
            lv[t >> 1] = pack_bf2(l0, l1);
        }
        *(uint4*)&g_ubh[h][n][sbase + segl * 8] = make_uint4(hv[0], hv[1], hv[2], hv[3]);
        *(uint4*)&g_ubl[h][n][sbase + segl * 8] = make_uint4(lv[0], lv[1], lv[2], lv[3]);
    }
}

// ================ GEMM-A: G[64,512] = T @ ub^T (3 hi/lo terms) ==========
#define GA_AROWS 64
#define GA_AELE  (GA_AROWS * ASTRIDE)
#define GA_ABYTES (GA_AELE * 2)
#define GA_BELE  (128 * ASTRIDE)
#define GA_STG   (GA_ABYTES + GA_BELE * 2)
#define GA_SMEM  (2 * GA_STG)

__global__ __launch_bounds__(128) void k_gemm_g() {
    extern __shared__ char dsm[];
    int q = blockIdx.x, h = blockIdx.y, tid = threadIdx.x;
    int wid = tid >> 5, lane = tid & 31;
    int n0 = q * 128;
    int warpM = wid & 1, warpN = wid >> 1;
    int m0 = warpM * 32, nw0 = warpN * 64;
    int tg = lane >> 2, tq = lane & 3;
    uint32_t sbase = smem_u32(dsm);
    uint32_t aOff = (uint32_t)(((m0 + (lane & 15)) * ASTRIDE + (lane >> 4) * 8) * 2);
    uint32_t bOff = (uint32_t)(((nw0 + (lane & 7) + ((lane >> 4) & 1) * 8) * ASTRIDE
                                + ((lane >> 3) & 1) * 8) * 2);

    float acc[2][8][4];
    #pragma unroll
    for (int mf = 0; mf < 2; mf++)
        #pragma unroll
        for (int nf = 0; nf < 8; nf++)
            #pragma unroll
            for (int v = 0; v < 4; v++) acc[mf][nf][v] = 0.f;

    const int NC = 6;
    #define GA_LOAD(c) do { \
        int st_ = (c) & 1; \
        uint32_t sA = sbase + st_ * GA_STG; \
        uint32_t sB = sA + GA_ABYTES; \
        int kc = ((c) & 1) * 64; \
        const __nv_bfloat16* asrc = ((c) >= 4) ? &g_Tl[h][0][kc] : &g_Th[h][0][kc]; \
        const __nv_bfloat16* bsrc = ((c) == 2 || (c) == 3) ? &g_ubl[h][n0][kc] : &g_ubh[h][n0][kc]; \
        _Pragma("unroll") \
        for (int it = 0; it < 4; it++) { \
            int idx = tid + 128 * it; \
            int row = idx >> 3, cu = idx & 7; \
            CP16(sA + row * (ASTRIDE * 2) + cu * 16, (const char*)asrc + row * 256 + cu * 16); \
        } \
        _Pragma("unroll") \
        for (int it = 0; it < 8; it++) { \
            int idx = tid + 128 * it; \
            int row = idx >> 3, cu = idx & 7; \
            CP16(sB + row * (ASTRIDE * 2) + cu * 16, (const char*)bsrc + row * 256 + cu * 16); \
        } \
        CP_COMMIT(); \
    } while (0)

    GA_LOAD(0);
    #pragma unroll 1
    for (int c = 0; c < NC; c++) {
        if (c + 1 < NC) { GA_LOAD(c + 1); CP_WAIT1(); }
        else            { CP_WAIT0(); }
        __syncthreads();
        uint32_t sA = sbase + (c & 1) * GA_STG;
        uint32_t sB = sA + GA_ABYTES;
        uint32_t aAddr = sA + aOff;
        uint32_t bAddr = sB + bOff;
        #pragma unroll
        for (int ks = 0; ks < 4; ks++) {
            uint32_t afr[2][4];
            LDSM4(afr[0], aAddr + ks * 32);
            LDSM4(afr[1], aAddr + 16 * ASTRIDE * 2 + ks * 32);
            #pragma unroll
            for (int p = 0; p < 4; p++) {
                uint32_t bfr[4];
                LDSM4(bfr, bAddr + p * 16 * ASTRIDE * 2 + ks * 32);
                #pragma unroll
                for (int sub = 0; sub < 2; sub++) {
                    int nf = p * 2 + sub;
                    uint32_t b0 = bfr[sub * 2], b1 = bfr[sub * 2 + 1];
                    #pragma unroll
                    for (int mf = 0; mf < 2; mf++)
                        MMA16816(acc[mf][nf][0], acc[mf][nf][1], acc[mf][nf][2], acc[mf][nf][3],
                                 afr[mf][0], afr[mf][1], afr[mf][2], afr[mf][3], b0, b1);
                }
            }
        }
        __syncthreads();
    }
    #undef GA_LOAD
    #pragma unroll
    for (int mf = 0; mf < 2; mf++) {
        int i = m0 + mf * 16 + tg;
        #pragma unroll
        for (int nf = 0; nf < 8; nf++) {
            int n = n0 + nw0 + nf * 8 + tq * 2;
            *(float2*)&g_G[h][i][n]     = make_float2(acc[mf][nf][0], acc[mf][nf][1]);
            *(float2*)&g_G[h][i + 8][n] = make_float2(acc[mf][nf][2], acc[mf][nf][3]);
        }
    }
}

// ---- scan: H_j = P H_{j-1} + G_j ; G prefetch, 1 barrier/iter ----------
__global__ __launch_bounds__(64) void k_scan() {
    int h = blockIdx.x >> 2, cq = blockIdx.x & 3, i = threadIdx.x;
    float P[KD];
    #pragma unroll
    for (int kq = 0; kq < KD; kq += 4) {
        float4 p = *(const float4*)&g_P[h][i][kq];
        P[kq] = p.x; P[kq + 1] = p.y; P[kq + 2] = p.z; P[kq + 3] = p.w;
    }
    __shared__ float hs[2][KD][4];
    float hv[4] = {0.f, 0.f, 0.f, 0.f};
    float4 gnext = *(const float4*)&g_G[h][i][cq * 4];
    #pragma unroll 1
    for (int j = 0; j < JJ; j++) {
        int buf = j & 1;
        #pragma unroll
        for (int cch = 0; cch < 4; cch++) {
            int n = j * NCH + cq * 4 + cch;
            __nv_bfloat16 hi = __float2bfloat16(hv[cch]);
            g_Hbh[h][n][i] = hi;
            g_Hbl[h][n][i] = __float2bfloat16(hv[cch] - __bfloat162float(hi));
        }
        *(float4*)&hs[buf][i][0] = make_float4(hv[0], hv[1], hv[2], hv[3]);
        float4 gcur = gnext;
        __syncthreads();
        if (j + 1 < JJ)
            gnext = *(const float4*)&g_G[h][i][(j + 1) * NCH + cq * 4];
        float acc[4] = {gcur.x, gcur.y, gcur.z, gcur.w};
        #pragma unroll
        for (int kq = 0; kq < KD; kq++) {
            float4 hk = *(const float4*)&hs[buf][kq][0];
            acc[0] = fmaf(P[kq], hk.x, acc[0]);
            acc[1] = fmaf(P[kq], hk.y, acc[1]);
            acc[2] = fmaf(P[kq], hk.z, acc[2]);
            acc[3] = fmaf(P[kq], hk.w, acc[3]);
        }
        hv[0] = acc[0]; hv[1] = acc[1]; hv[2] = acc[2]; hv[3] = acc[3];
    }
}

// ==== GEMM-B: y = [Toep(k)|Hank(s)] @ [u|H]^T — A from LUT, B streamed ===
#define YSTG  (64 * ASTRIDE * 2)     // 9216 B : one 64-row B tile
#define YSMEM (4 * YSTG)             // 4-stage ring

__global__ __launch_bounds__(128) void k_gemm_y(float* __restrict__ y) {
    extern __shared__ char dsm[];
    __shared__ uint32_t sLUT[896];
    int qb = blockIdx.x, h = blockIdx.y, tid = threadIdx.x;
    int wid = tid >> 5, lane = tid & 31;
    int n0 = qb * 64;
    int rb0 = wid * 16;                 // mf0 row block
    int rb1 = 112 - wid * 16;           // mf1 row block (balanced pairing)
    int tg = lane >> 2, tq = lane & 3;
    uint32_t smStg = smem_u32(dsm);
    uint32_t bOff = (uint32_t)(((((lane & 7) + ((lane >> 4) & 1) * 8)) * ASTRIDE
                                + ((lane >> 3) & 1) * 8) * 2);
    #pragma unroll
    for (int it = 0; it < 7; it++) {
        int idx = tid + 128 * it;
        sLUT[idx] = g_LUT[h][idx];      // 7*128 = 896 exactly
    }

    float acc[2][8][4];
    #pragma unroll
    for (int mf = 0; mf < 2; mf++)
        #pragma unroll
        for (int nf = 0; nf < 8; nf++)
            #pragma unroll
            for (int v = 0; v < 4; v++) acc[mf][nf][v] = 0.f;

    #define YB_LOAD(t) do { \
        const __nv_bfloat16* bsrc; int brs; \
        switch (t) { \
            case 0: bsrc = &g_ubh[h][n0][0];  brs = 256; break; \
            case 1: bsrc = &g_ubh[h][n0][64]; brs = 256; break; \
            case 2: bsrc = &g_Hbh[h][n0][0];  brs = 128; break; \
            case 3: bsrc = &g_ubl[h][n0][0];  brs = 256; break; \
            case 4: bsrc = &g_ubl[h][n0][64]; brs = 256; break; \
            default: bsrc = &g_Hbl[h][n0][0]; brs = 128; break; } \
        uint32_t sB = smStg + ((t) & 3) * YSTG; \
        _Pragma("unroll") \
        for (int it = 0; it < 4; it++) { \
            int idx = tid + 128 * it; \
            int row = idx >> 3, cu = idx & 7; \
            CP16(sB + row * (ASTRIDE * 2) + cu * 16, (const char*)bsrc + row * brs + cu * 16); \
        } \
        CP_COMMIT(); \
    } while (0)

    // One B tile, npass W-terms; B fragments loaded once per ks.
    #define Y_TILE(hank, kc, npass) do { \
        _Pragma("unroll") \
        for (int ks = 0; ks < 4; ks++) { \
            int sig0 = (kc) * 64 + ks * 16; \
            bool live0 = true, live1 = true; \
            if (!(hank)) { \
                live1 = (sig0 <= rb1 + 15); \
                if (!live1) continue;           /* rb1 > rb0: both dead */ \
                live0 = (sig0 <= rb0 + 15); \
            } \
            uint32_t bfr[4][4]; \
            _Pragma("unroll") \
            for (int p = 0; p < 4; p++) \
                LDSM4(bfr[p], bAddr + p * 16 * ASTRIDE * 2 + ks * 32); \
            _Pragma("unroll") \
            for (int term = 0; term < (npass); term++) { \
                const uint32_t* lutp = (hank) ? (term ? sLUT + 704 : sLUT + 512) \
                                              : (term ? sLUT + 256 : sLUT); \
                uint32_t A0[4], A1[4]; \
                if (hank) { \
                    int x0 = rb0 + 1 + ks * 16 + tq * 2 + tg; \
                    int x1 = rb1 + 1 + ks * 16 + tq * 2 + tg; \
                    uint32_t h0 = lutp[x0], h1 = lutp[x0 + 8], h2 = lutp[x0 + 16]; \
                    uint32_t h3 = lutp[x1], h4 = lutp[x1 + 8], h5 = lutp[x1 + 16]; \
                    A0[0] = h0; A0[1] = h1; A0[2] = h1; A0[3] = h2; \
                    A1[0] = h3; A1[1] = h4; A1[2] = h4; A1[3] = h5; \
                } else { \
                    int x0 = 128 + rb0 + tg - sig0 - tq * 2; \
                    int x1 = 128 + rb1 + tg - sig0 - tq * 2; \
                    uint32_t w0 = lutp[x0], w1 = lutp[x0 + 8], w2 = lutp[x0 - 8]; \
                    uint32_t w3 = lutp[x1], w4 = lutp[x1 + 8], w5 = lutp[x1 - 8]; \
                    A0[0] = w0; A0[1] = w1; A0[2] = w2; A0[3] = w0; \
                    A1[0] = w3; A1[1] = w4; A1[2] = w5; A1[3] = w3; \
                } \
                _Pragma("unroll") \
                for (int p = 0; p < 4; p++) { \
                    _Pragma("unroll") \
                    for (int sub = 0; sub < 2; sub++) { \
                        int nf = p * 2 + sub; \
                        uint32_t b0 = bfr[p][sub * 2], b1 = bfr[p][sub * 2 + 1]; \
                        if (live0) \
                            MMA16816(acc[0][nf][0], acc[0][nf][1], acc[0][nf][2], acc[0][nf][3], \
                                     A0[0], A0[1], A0[2], A0[3], b0, b1); \
                        if (live1) \
                            MMA16816(acc[1][nf][0], acc[1][nf][1], acc[1][nf][2], acc[1][nf][3], \
                                     A1[0], A1[1], A1[2], A1[3], b0, b1); \
                    } \
                } \
            } \
        } \
    } while (0)

    YB_LOAD(0); YB_LOAD(1); YB_LOAD(2);
    #pragma unroll 1
    for (int t = 0; t < 6; t++) {
        if (t <= 3)      CP_WAIT2();
        else if (t == 4) CP_WAIT1();
        else             CP_WAIT0();
        __syncthreads();
        if (t + 3 < 6) YB_LOAD(t + 3);
        uint32_t bAddr = smStg + (t & 3) * YSTG + bOff;
        switch (t) {
            case 0: Y_TILE(0, 0, 2); break;
            case 1: Y_TILE(0, 1, 2); break;
            case 2: Y_TILE(1, 0, 2); break;
            case 3: Y_TILE(0, 0, 1); break;
            case 4: Y_TILE(0, 1, 1); break;
            default: Y_TILE(1, 0, 1); break;
        }
    }
    #undef Y_TILE
    #undef YB_LOAD

    // epilogue -> y
    #pragma unroll
    for (int mf = 0; mf < 2; mf++) {
        int tau = (mf == 0 ? rb0 : rb1) + tg;
        #pragma unroll
        for (int nf = 0; nf < 8; nf++) {
            int n = n0 + nf * 8 + tq * 2;
            int j = n >> 4, b = (n >> 2) & 3, r = n & 3;
            size_t base = ((size_t)(b * LL + j * CC + tau)) * DD + h * NH + r;
            *(float2*)&y[base]          = make_float2(acc[mf][nf][0], acc[mf][nf][1]);
            *(float2*)&y[base + 8 * DD] = make_float2(acc[mf][nf][2], acc[mf][nf][3]);
        }
    }
}

// ---------------- launch ----------------
extern "C" void kernel_launch(void* const* d_in, const int* in_sizes, int n_in,
                              void* d_out, int out_size) {
    const float* u = (const float*)d_in[0];
    const float* a = (const float*)d_in[1];
    const float* b = (const float*)d_in[2];
    const float* c = (const float*)d_in[3];
    float* y = (float*)d_out;

    cudaFuncSetAttribute(k_gemm_g, cudaFuncAttributeMaxDynamicSharedMemorySize, GA_SMEM);
    cudaFuncSetAttribute(k_gemm_y, cudaFuncAttributeMaxDynamicSharedMemorySize, YSMEM);

    // fork: k_tr (memory) runs concurrently with k_nf+k_precomp (compute)
    cudaStream_t s1;
    cudaEvent_t e0, e1;
    bool forked = (cudaStreamCreateWithFlags(&s1, cudaStreamNonBlocking) == cudaSuccess) &&
                  (cudaEventCreateWithFlags(&e0, cudaEventDisableTiming) == cudaSuccess) &&
                  (cudaEventCreateWithFlags(&e1, cudaEventDisableTiming) == cudaSuccess);

    if (forked) {
        cudaEventRecord(e0, 0);
        cudaStreamWaitEvent(s1, e0, 0);
        k_tr<<<4096, 256, 0, s1>>>(u);
        cudaEventRecord(e1, s1);
    } else {
        k_tr<<<4096, 256>>>(u);
    }
    k_nf<<<1, 256>>>(a);
    k_precomp<<<NK, 256>>>(a, b, c);
    if (forked) cudaStreamWaitEvent(0, e1, 0);
    k_gemm_g<<<dim3(4, NK), 128, GA_SMEM>>>();
    k_scan<<<NK * 4, 64>>>();
    k_gemm_y<<<dim3(8, NK), 128, YSMEM>>>(y);
    // s1/e0/e1 intentionally not destroyed (graph-capture safety).
}